// round 2
// baseline (speedup 1.0000x reference)
#include <cuda_runtime.h>

#define NXg 512
#define NYg 512
#define NTg 300
#define NCELL (NXg * NYg)

// Ping-pong field buffers (state across the 300 steps within one launch).
__device__ float g_bufA[NCELL];
__device__ float g_bufB[NCELL];

__global__ void wave_zero_kernel() {
    int idx = blockIdx.x * blockDim.x + threadIdx.x;
    if (idx < NCELL) {
        g_bufA[idx] = 0.0f;
        g_bufB[idx] = 0.0f;
    }
}

// PML ramp: b_vals[k] = 0.5 * (k/20)^3, k in [0,20]
__device__ __forceinline__ float pml_ramp(int k) {
    float t = (float)k * (1.0f / 20.0f);
    return 0.5f * t * t * t;
}

__global__ void __launch_bounds__(256)
wave_step_kernel(const float* __restrict__ c2,
                 const float* __restrict__ msrc,
                 const float* __restrict__ xsrc,
                 float* __restrict__ d_final,
                 int t) {
    int j = blockIdx.x * blockDim.x + threadIdx.x;   // contiguous dim
    int i = blockIdx.y * blockDim.y + threadIdx.y;
    int idx = i * NYg + j;

    // Buffer roles: t even -> un1=A, un2=B, write B ; t odd -> un1=B, un2=A, write A
    const float* un1 = (t & 1) ? g_bufB : g_bufA;
    const float* un2 = (t & 1) ? g_bufA : g_bufB;
    float* out = (t == NTg - 1) ? d_final : ((t & 1) ? g_bufA : g_bufB);

    float u1c = un1[idx];
    float up = (i > 0)       ? un1[idx - NYg] : 0.0f;
    float dn = (i < NXg - 1) ? un1[idx + NYg] : 0.0f;
    float lf = (j > 0)       ? un1[idx - 1]   : 0.0f;
    float rt = (j < NYg - 1) ? un1[idx + 1]   : 0.0f;
    float lap = up + dn + lf + rt - 4.0f * u1c;

    // Analytic PML damping b(i,j)
    float bx = 0.0f, by = 0.0f;
    if (i <= 20) bx = pml_ramp(20 - i);
    else if (i >= NXg - 22 && i <= NXg - 2) bx = pml_ramp(i - (NXg - 22));
    if (j <= 20) by = pml_ramp(20 - j);
    else if (j >= NYg - 22 && j <= NYg - 2) by = pml_ramp(j - (NYg - 22));
    float b = sqrtf(bx * bx + by * by);

    // dt=0.5: inv_dt2=4, C2=8, C1=1/(4+b), C3=4-b
    float xi = __ldg(&xsrc[t]);
    float num = 8.0f * u1c - (4.0f - b) * un2[idx] + c2[idx] * lap + msrc[idx] * xi;
    out[idx] = num / (4.0f + b);
}

extern "C" void kernel_launch(void* const* d_in, const int* in_sizes, int n_in,
                              void* d_out, int out_size) {
    const float* x    = (const float*)d_in[0];   // (300,) source amplitude
    const float* c2   = (const float*)d_in[1];   // (512,512)
    const float* msrc = (const float*)d_in[2];   // (512,512)
    // d_in[3] = mask_probe, unused by the reference output
    float* out = (float*)d_out;

    wave_zero_kernel<<<NCELL / 256, 256>>>();

    dim3 blk(128, 2);
    dim3 grd(NYg / 128, NXg / 2);
    for (int t = 0; t < NTg; ++t) {
        wave_step_kernel<<<grd, blk>>>(c2, msrc, x, out, t);
    }
}

// round 3
// speedup vs baseline: 1.2168x; 1.2168x over previous
#include <cuda_runtime.h>

#define NXg 512
#define NYg 512
#define NTg 300
#define NCELL (NXg * NYg)

#define TILE 32
#define KSTEP 10
#define NLAUNCH (NTg / KSTEP)          // 30
#define RREG (TILE + 2 * KSTEP)        // 52
#define RPITCH (RREG + 1)              // 53 (odd -> conflict-free columns)
#define SSZ (RREG * RPITCH)

// Two ping-pong PAIRS across launches (avoids cross-block races within a launch).
__device__ float g_u1a[NCELL];
__device__ float g_u2a[NCELL];
__device__ float g_u1b[NCELL];
__device__ float g_u2b[NCELL];

__global__ void wave_zero_kernel() {
    int idx = blockIdx.x * blockDim.x + threadIdx.x;
    if (idx < NCELL) {
        g_u1a[idx] = 0.0f;
        g_u2a[idx] = 0.0f;
    }
}

// PML ramp: b_vals[k] = 0.5 * (k/20)^3, k in [0,20]
__device__ __forceinline__ float pml_ramp(int k) {
    float t = (float)k * (1.0f / 20.0f);
    return 0.5f * t * t * t;
}

__device__ __forceinline__ float pml_b(int gi, int gj) {
    float bx = 0.0f, by = 0.0f;
    if (gi <= 20) bx = pml_ramp(20 - gi);
    else if (gi >= NXg - 22 && gi <= NXg - 2) bx = pml_ramp(gi - (NXg - 22));
    if (gj <= 20) by = pml_ramp(20 - gj);
    else if (gj >= NYg - 22 && gj <= NYg - 2) by = pml_ramp(gj - (NYg - 22));
    return sqrtf(bx * bx + by * by);
}

__global__ void __launch_bounds__(256)
wave_tb_kernel(const float* __restrict__ c2,
               const float* __restrict__ msrc,
               const float* __restrict__ xsrc,
               const float* __restrict__ rd1,   // u at t0
               const float* __restrict__ rd2,   // u at t0-1
               float* __restrict__ wr1,
               float* __restrict__ wr2,
               float* __restrict__ d_final,
               int t0, int isLast) {
    extern __shared__ float smem[];
    float* sU1 = smem;                 // time-level ping
    float* sU2 = smem + SSZ;           // time-level pong
    float* sP  = smem + 2 * SSZ;       // 8/(4+b)
    float* sQ  = smem + 3 * SSZ;       // (4-b)/(4+b)
    float* sRc = smem + 4 * SSZ;       // c2/(4+b)
    float* sS  = smem + 5 * SSZ;       // msrc/(4+b)
    __shared__ float sX[KSTEP];

    const int tid = threadIdx.x;
    const int gi0 = blockIdx.y * TILE;
    const int gj0 = blockIdx.x * TILE;
    const int ri0 = gi0 - KSTEP;
    const int rj0 = gj0 - KSTEP;

    if (tid < KSTEP) sX[tid] = xsrc[t0 + tid];

    // ---- Load region: fields + fused coefficients ----
    for (int r = tid; r < RREG * RREG; r += 256) {
        int ri = r / RREG, rj = r % RREG;
        int gi = ri0 + ri, gj = rj0 + rj;
        int si = ri * RPITCH + rj;
        bool in = ((unsigned)gi < NXg) && ((unsigned)gj < NYg);
        int g = gi * NYg + gj;
        float u1 = 0.0f, u2 = 0.0f, P = 0.0f, Q = 0.0f, Rc = 0.0f, S = 0.0f;
        if (in) {
            u1 = rd1[g];
            u2 = rd2[g];
            float b = pml_b(gi, gj);
            float rb = 1.0f / (4.0f + b);
            P = 8.0f * rb;
            Q = (4.0f - b) * rb;
            Rc = c2[g] * rb;
            S = msrc[g] * rb;
        }
        sU1[si] = u1; sU2[si] = u2;
        sP[si] = P; sQ[si] = Q; sRc[si] = Rc; sS[si] = S;
    }

    // Erosion applies only on sides where the region edge lies inside the domain.
    const bool erLoI = (ri0 >= 0);
    const bool erHiI = (gi0 + TILE + KSTEP <= NXg);
    const bool erLoJ = (rj0 >= 0);
    const bool erHiJ = (gj0 + TILE + KSTEP <= NYg);

    __syncthreads();

    // ---- K in-smem time steps ----
    #pragma unroll
    for (int s = 0; s < KSTEP; ++s) {
        float* cur = (s & 1) ? sU2 : sU1;   // newest level (t0+s)
        float* old = (s & 1) ? sU1 : sU2;   // t0+s-1, overwritten with t0+s+1
        const float xi = sX[s];
        const int li = erLoI ? s + 1 : 0;
        const int hi = erHiI ? RREG - 2 - s : RREG - 1;
        const int lj = erLoJ ? s + 1 : 0;
        const int hj = erHiJ ? RREG - 2 - s : RREG - 1;

        for (int r = tid; r < RREG * RREG; r += 256) {
            int ri = r / RREG, rj = r % RREG;
            if (ri < li || ri > hi || rj < lj || rj > hj) continue;
            int gi = ri0 + ri, gj = rj0 + rj;
            if (((unsigned)gi >= NXg) || ((unsigned)gj >= NYg)) continue;
            int si = ri * RPITCH + rj;
            float uc = cur[si];
            float lap = cur[si - RPITCH] + cur[si + RPITCH]
                      + cur[si - 1] + cur[si + 1] - 4.0f * uc;
            // in-place: old[si] is read only by this thread
            old[si] = sP[si] * uc - sQ[si] * old[si] + sRc[si] * lap + sS[si] * xi;
        }
        __syncthreads();
    }

    // After KSTEP=10 (even) steps: newest (t0+K) in sU1, t0+K-1 in sU2.
    for (int r = tid; r < TILE * TILE; r += 256) {
        int oi = r / TILE, oj = r % TILE;
        int gi = gi0 + oi, gj = gj0 + oj;
        int si = (KSTEP + oi) * RPITCH + (KSTEP + oj);
        int g = gi * NYg + gj;
        if (isLast) {
            d_final[g] = sU1[si];
        } else {
            wr1[g] = sU1[si];
            wr2[g] = sU2[si];
        }
    }
}

extern "C" void kernel_launch(void* const* d_in, const int* in_sizes, int n_in,
                              void* d_out, int out_size) {
    const float* x    = (const float*)d_in[0];   // (300,)
    const float* c2   = (const float*)d_in[1];   // (512,512)
    const float* msrc = (const float*)d_in[2];   // (512,512)
    float* out = (float*)d_out;

    static bool attr_done = false;
    if (!attr_done) {
        cudaFuncSetAttribute(wave_tb_kernel,
                             cudaFuncAttributeMaxDynamicSharedMemorySize,
                             6 * SSZ * (int)sizeof(float));
        attr_done = true;
    }

    // Resolve device-global buffer addresses (host-side, capture-safe).
    float *u1a, *u2a, *u1b, *u2b;
    cudaGetSymbolAddress((void**)&u1a, g_u1a);
    cudaGetSymbolAddress((void**)&u2a, g_u2a);
    cudaGetSymbolAddress((void**)&u1b, g_u1b);
    cudaGetSymbolAddress((void**)&u2b, g_u2b);

    wave_zero_kernel<<<NCELL / 256, 256>>>();

    dim3 grd(NYg / TILE, NXg / TILE);   // 16 x 16 = 256 blocks
    size_t shmem = 6 * SSZ * sizeof(float);
    for (int l = 0; l < NLAUNCH; ++l) {
        bool even = (l & 1) == 0;
        const float* r1 = even ? u1a : u1b;
        const float* r2 = even ? u2a : u2b;
        float* w1 = even ? u1b : u1a;
        float* w2 = even ? u2b : u2a;
        wave_tb_kernel<<<grd, 256, shmem>>>(c2, msrc, x, r1, r2, w1, w2, out,
                                            l * KSTEP, l == NLAUNCH - 1 ? 1 : 0);
    }
}

// round 4
// speedup vs baseline: 1.7024x; 1.3991x over previous
#include <cuda_runtime.h>

#define NXg 512
#define NYg 512
#define NTg 300
#define NCELL (NXg * NYg)

#define TI 64                // tile rows per block
#define TJ 32                // tile cols per block
#define KSTEP 10
#define NLAUNCH (NTg / KSTEP)     // 30
#define RI (TI + 2 * KSTEP)       // 84 region rows
#define RJ (TJ + 2 * KSTEP)       // 52 region cols == pitch
#define GUARD RJ                  // one guard row above & below
#define USZ (RI * RJ + 2 * GUARD) // 4472 floats per time-level
#define NROW 11                   // ceil(84/8) rows per thread
#define NTHR 416                  // 52 x 8

// Ping-pong pairs across launches.
__device__ float g_u1a[NCELL];
__device__ float g_u2a[NCELL];
__device__ float g_u1b[NCELL];
__device__ float g_u2b[NCELL];

__global__ void wave_zero_kernel() {
    int idx = blockIdx.x * blockDim.x + threadIdx.x;
    if (idx < NCELL) {
        g_u1a[idx] = 0.0f;
        g_u2a[idx] = 0.0f;
    }
}

// PML ramp: b_vals[k] = 0.5 * (k/20)^3, k in [0,20]
__device__ __forceinline__ float pml_ramp(int k) {
    float t = (float)k * (1.0f / 20.0f);
    return 0.5f * t * t * t;
}

__device__ __forceinline__ float pml_b(int gi, int gj) {
    float bx = 0.0f, by = 0.0f;
    if (gi <= 20) bx = pml_ramp(20 - gi);
    else if (gi >= NXg - 22 && gi <= NXg - 2) bx = pml_ramp(gi - (NXg - 22));
    if (gj <= 20) by = pml_ramp(20 - gj);
    else if (gj >= NYg - 22 && gj <= NYg - 2) by = pml_ramp(gj - (NYg - 22));
    return sqrtf(bx * bx + by * by);
}

__global__ void __launch_bounds__(NTHR)
wave_tb_kernel(const float* __restrict__ c2,
               const float* __restrict__ msrc,
               const float* __restrict__ xsrc,
               const float* __restrict__ rd1,   // u at t0
               const float* __restrict__ rd2,   // u at t0-1
               float* __restrict__ wr1,
               float* __restrict__ wr2,
               float* __restrict__ d_final,
               int t0, int isLast) {
    __shared__ float sA[USZ];
    __shared__ float sB[USZ];
    __shared__ float sX[KSTEP];

    const int tx = threadIdx.x;            // 0..51  (column in region)
    const int ty = threadIdx.y;            // 0..7
    const int tid = ty * RJ + tx;

    const int gi0 = blockIdx.y * TI;
    const int gj0 = blockIdx.x * TJ;
    const int ri0 = gi0 - KSTEP;
    const int rj0 = gj0 - KSTEP;

    if (tid < KSTEP) sX[tid] = xsrc[t0 + tid];

    // Zero both levels including guards (out-of-domain stays 0 forever).
    for (int k = tid; k < USZ; k += NTHR) { sA[k] = 0.0f; sB[k] = 0.0f; }
    __syncthreads();

    // ---- Load fields + per-cell coefficients into registers ----
    float cP4[NROW], cQ[NROW], cRc[NROW], cSb[NROW];
    #pragma unroll
    for (int r = 0; r < NROW; ++r) {
        int ir = ty + 8 * r;
        int irc = ir > RI - 1 ? RI - 1 : ir;
        int gi = ri0 + irc;
        int gj = rj0 + tx;
        bool in = (ir <= RI - 1) && ((unsigned)gi < NXg) && ((unsigned)gj < NYg);
        float P4 = 0.0f, Qv = 0.0f, Rcv = 0.0f, Sbv = 0.0f;
        if (in) {
            int g = gi * NYg + gj;
            int si = GUARD + irc * RJ + tx;
            sA[si] = rd1[g];
            sB[si] = rd2[g];
            float b = pml_b(gi, gj);
            float rb = 1.0f / (4.0f + b);
            float c2v = c2[g];
            P4 = (8.0f - 4.0f * c2v) * rb;   // coeff of center
            Qv = 8.0f * rb - 1.0f;           // (4-b)/(4+b)
            Rcv = c2v * rb;                  // coeff of 4-neighbor sum
            Sbv = msrc[g] * rb;              // source coeff (times xi)
        }
        cP4[r] = P4; cQ[r] = Qv; cRc[r] = Rcv; cSb[r] = Sbv;
    }

    // Domain clamps (region-relative indices)
    const int dloI = (ri0 < 0) ? -ri0 : 0;
    const int dhiI = (ri0 + RI - 1 > NXg - 1) ? (NXg - 1 - ri0) : (RI - 1);
    const int dloJ = (rj0 < 0) ? -rj0 : 0;
    const int dhiJ = (rj0 + RJ - 1 > NYg - 1) ? (NYg - 1 - rj0) : (RJ - 1);
    const bool erLoI = (ri0 >= 0);
    const bool erHiI = (ri0 + RI <= NXg);
    const bool erLoJ = (rj0 >= 0);
    const bool erHiJ = (rj0 + RJ <= NYg);

    __syncthreads();

    float* cur = sA;   // level t0
    float* old = sB;   // level t0-1, overwritten with t0+1
    #pragma unroll 1
    for (int s = 0; s < KSTEP; ++s) {
        const float xi = sX[s];
        int loI = erLoI ? s + 1 : dloI; if (loI < dloI) loI = dloI;
        int hiI = erHiI ? RI - 2 - s : dhiI; if (hiI > dhiI) hiI = dhiI;
        int loJ = erLoJ ? s + 1 : dloJ; if (loJ < dloJ) loJ = dloJ;
        int hiJ = erHiJ ? RJ - 2 - s : dhiJ; if (hiJ > dhiJ) hiJ = dhiJ;
        const bool jok = (tx >= loJ) && (tx <= hiJ);

        #pragma unroll
        for (int r = 0; r < NROW; ++r) {
            int ir = ty + 8 * r;
            int irc = ir > RI - 1 ? RI - 1 : ir;
            int si = GUARD + irc * RJ + tx;
            float uc = cur[si];
            float sum = (cur[si - 1] + cur[si + 1]) + (cur[si - RJ] + cur[si + RJ]);
            float v = cP4[r] * uc;
            v = fmaf(-cQ[r], old[si], v);
            v = fmaf(cRc[r], sum, v);
            v = fmaf(cSb[r], xi, v);
            if (jok && ir >= loI && ir <= hiI) old[si] = v;
        }
        __syncthreads();
        float* t = cur; cur = old; old = t;
    }

    // cur = t0+KSTEP, old = t0+KSTEP-1. Write back the 64x32 tile.
    #pragma unroll
    for (int r = 0; r < NROW; ++r) {
        int ir = ty + 8 * r;
        if (ir >= KSTEP && ir < KSTEP + TI && tx >= KSTEP && tx < KSTEP + TJ) {
            int gi = ri0 + ir;
            int gj = rj0 + tx;
            int g = gi * NYg + gj;
            int si = GUARD + ir * RJ + tx;
            if (isLast) {
                d_final[g] = cur[si];
            } else {
                wr1[g] = cur[si];
                wr2[g] = old[si];
            }
        }
    }
}

extern "C" void kernel_launch(void* const* d_in, const int* in_sizes, int n_in,
                              void* d_out, int out_size) {
    const float* x    = (const float*)d_in[0];   // (300,)
    const float* c2   = (const float*)d_in[1];   // (512,512)
    const float* msrc = (const float*)d_in[2];   // (512,512)
    float* out = (float*)d_out;

    float *u1a, *u2a, *u1b, *u2b;
    cudaGetSymbolAddress((void**)&u1a, g_u1a);
    cudaGetSymbolAddress((void**)&u2a, g_u2a);
    cudaGetSymbolAddress((void**)&u1b, g_u1b);
    cudaGetSymbolAddress((void**)&u2b, g_u2b);

    wave_zero_kernel<<<NCELL / 256, 256>>>();

    dim3 grd(NYg / TJ, NXg / TI);   // (16, 8) = 128 blocks
    dim3 blk(RJ, 8);                // (52, 8) = 416 threads
    for (int l = 0; l < NLAUNCH; ++l) {
        bool even = (l & 1) == 0;
        const float* r1 = even ? u1a : u1b;
        const float* r2 = even ? u2a : u2b;
        float* w1 = even ? u1b : u1a;
        float* w2 = even ? u2b : u2a;
        wave_tb_kernel<<<grd, blk>>>(c2, msrc, x, r1, r2, w1, w2, out,
                                     l * KSTEP, l == NLAUNCH - 1 ? 1 : 0);
    }
}

// round 6
// speedup vs baseline: 2.9000x; 1.7035x over previous
#include <cuda_runtime.h>

#define NXg 512
#define NYg 512
#define NTg 300
#define NCELL (NXg * NYg)

#define TI 64                     // tile rows per block
#define TJ 32                     // tile cols per block
#define KSTEP 10
#define NLAUNCH (NTg / KSTEP)     // 30
#define RI (TI + 2 * KSTEP)       // 84 region rows
#define RJ (TJ + 2 * KSTEP)       // 52 region cols
#define PITCH (RJ + 2)            // 54: guard col on each side
#define SROWS (RI + 2)            // 86: guard row top & bottom
#define SSZ (SROWS * PITCH)       // 4644 floats per level
#define NSEG 6                    // contiguous rows per thread
#define NTY 14                    // 14 * 6 = 84 rows
#define NTHR (RJ * NTY)           // 52 x 14 = 728 threads

// Ping-pong pairs across launches.
__device__ float g_u1a[NCELL];
__device__ float g_u2a[NCELL];
__device__ float g_u1b[NCELL];
__device__ float g_u2b[NCELL];

__global__ void wave_zero_kernel() {
    int idx = blockIdx.x * blockDim.x + threadIdx.x;
    if (idx < NCELL) {
        g_u1a[idx] = 0.0f;
        g_u2a[idx] = 0.0f;
    }
}

// PML ramp: b_vals[k] = 0.5 * (k/20)^3, k in [0,20]
__device__ __forceinline__ float pml_ramp(int k) {
    float t = (float)k * (1.0f / 20.0f);
    return 0.5f * t * t * t;
}

__device__ __forceinline__ float pml_b(int gi, int gj) {
    float bx = 0.0f, by = 0.0f;
    if (gi <= 20) bx = pml_ramp(20 - gi);
    else if (gi >= NXg - 22 && gi <= NXg - 2) bx = pml_ramp(gi - (NXg - 22));
    if (gj <= 20) by = pml_ramp(20 - gj);
    else if (gj >= NYg - 22 && gj <= NYg - 2) by = pml_ramp(gj - (NYg - 22));
    return sqrtf(bx * bx + by * by);
}

__global__ void __launch_bounds__(NTHR)
wave_tb_kernel(const float* __restrict__ c2,
               const float* __restrict__ msrc,
               const float* __restrict__ xsrc,
               const float* __restrict__ rd1,   // u at t0
               const float* __restrict__ rd2,   // u at t0-1
               float* __restrict__ wr1,
               float* __restrict__ wr2,
               float* __restrict__ d_final,
               int t0, int isLast) {
    __shared__ float s0[SSZ];
    __shared__ float s1[SSZ];
    __shared__ float sX[KSTEP];

    const int tx = threadIdx.x;            // 0..51  region column
    const int ty = threadIdx.y;            // 0..13  segment id (rows ty*6 .. ty*6+5)
    const int tid = ty * RJ + tx;

    const int gi0 = blockIdx.y * TI;
    const int gj0 = blockIdx.x * TJ;
    const int ri0 = gi0 - KSTEP;
    const int rj0 = gj0 - KSTEP;
    const int r0 = ty * NSEG;              // first owned region row
    const int base = (r0 + 1) * PITCH + (tx + 1);

    if (tid < KSTEP) sX[tid] = xsrc[t0 + tid];

    // Zero both levels incl. guards; out-of-domain cells stay 0 forever.
    for (int k = tid; k < SSZ; k += NTHR) { s0[k] = 0.0f; s1[k] = 0.0f; }

    // ---- Load fields (registers + s0) and coefficients (registers) ----
    float curR[NSEG], oldR[NSEG];
    float cP4[NSEG], cQ[NSEG], cRc[NSEG], cSb[NSEG];
    const int gj = rj0 + tx;
    const bool jin = ((unsigned)gj < NYg);
    #pragma unroll
    for (int k = 0; k < NSEG; ++k) {
        int gi = ri0 + r0 + k;
        bool in = jin && ((unsigned)gi < NXg);
        float u1 = 0.0f, u2 = 0.0f, P4 = 0.0f, Qv = 0.0f, Rcv = 0.0f, Sbv = 0.0f;
        if (in) {
            int g = gi * NYg + gj;
            u1 = rd1[g];
            u2 = rd2[g];
            float b = pml_b(gi, gj);
            float rb = 1.0f / (4.0f + b);
            float c2v = c2[g];
            P4 = (8.0f - 4.0f * c2v) * rb;   // center coeff
            Qv = (4.0f - b) * rb;            // old-level coeff
            Rcv = c2v * rb;                  // 4-neighbor-sum coeff
            Sbv = msrc[g] * rb;              // source coeff
        }
        curR[k] = u1; oldR[k] = u2;
        cP4[k] = P4; cQ[k] = Qv; cRc[k] = Rcv; cSb[k] = Sbv;
    }
    __syncthreads();     // zero-fill done before field STS
    #pragma unroll
    for (int k = 0; k < NSEG; ++k) s0[base + k * PITCH] = curR[k];
    __syncthreads();

    // ---- KSTEP in-smem/register time steps, branch-free inner loop ----
    #pragma unroll 1
    for (int s = 0; s < KSTEP; ++s) {
        const float* sc = (s & 1) ? s1 : s0;   // current level (neighbors)
        float* sn = (s & 1) ? s0 : s1;         // next level
        const float xi = sX[s];
        // prevUp streams the level-s value of the row above (fixes the
        // R5 bug where curR[k-1] had already been overwritten with s+1).
        float prevUp = sc[base - PITCH];       // segment-top neighbor (smem)
        #pragma unroll
        for (int k = 0; k < NSEG; ++k) {
            int si = base + k * PITCH;
            float up = prevUp;
            float dn = (k == NSEG - 1) ? sc[si + PITCH] : curR[k + 1];
            float lf = sc[si - 1];
            float rt = sc[si + 1];
            float v = cP4[k] * curR[k];
            v = fmaf(-cQ[k], oldR[k], v);
            v = fmaf(cRc[k], (up + dn) + (lf + rt), v);
            v = fmaf(cSb[k], xi, v);
            sn[si] = v;                 // unique writer; 0 out-of-domain (coeffs=0)
            prevUp = curR[k];           // level-s value before overwrite
            oldR[k] = curR[k];
            curR[k] = v;
        }
        __syncthreads();
    }

    // curR = level t0+KSTEP, oldR = t0+KSTEP-1. Write back the 64x32 tile.
    if (tx >= KSTEP && tx < KSTEP + TJ) {
        #pragma unroll
        for (int k = 0; k < NSEG; ++k) {
            int r = r0 + k;
            if (r >= KSTEP && r < KSTEP + TI) {
                int g = (ri0 + r) * NYg + gj;
                if (isLast) {
                    d_final[g] = curR[k];
                } else {
                    wr1[g] = curR[k];
                    wr2[g] = oldR[k];
                }
            }
        }
    }
}

extern "C" void kernel_launch(void* const* d_in, const int* in_sizes, int n_in,
                              void* d_out, int out_size) {
    const float* x    = (const float*)d_in[0];   // (300,)
    const float* c2   = (const float*)d_in[1];   // (512,512)
    const float* msrc = (const float*)d_in[2];   // (512,512)
    float* out = (float*)d_out;

    float *u1a, *u2a, *u1b, *u2b;
    cudaGetSymbolAddress((void**)&u1a, g_u1a);
    cudaGetSymbolAddress((void**)&u2a, g_u2a);
    cudaGetSymbolAddress((void**)&u1b, g_u1b);
    cudaGetSymbolAddress((void**)&u2b, g_u2b);

    wave_zero_kernel<<<NCELL / 256, 256>>>();

    dim3 grd(NYg / TJ, NXg / TI);   // (16, 8) = 128 blocks, 1 per SM
    dim3 blk(RJ, NTY);              // (52, 14) = 728 threads
    for (int l = 0; l < NLAUNCH; ++l) {
        bool even = (l & 1) == 0;
        const float* r1 = even ? u1a : u1b;
        const float* r2 = even ? u2a : u2b;
        float* w1 = even ? u1b : u1a;
        float* w2 = even ? u2b : u2a;
        wave_tb_kernel<<<grd, blk>>>(c2, msrc, x, r1, r2, w1, w2, out,
                                     l * KSTEP, l == NLAUNCH - 1 ? 1 : 0);
    }
}